// round 11
// baseline (speedup 1.0000x reference)
#include <cuda_runtime.h>

#define Bdim 2
#define Cdim 128
#define Tdim 4
#define S    16384      // T*H*W
#define NH   32
#define DHEAD 4
#define NTOK 1024       // T * (H/4) * (W/4)
#define TABSZ 6727      // (2T-1)*(2h-1)*(2w-1) = 7*31*31
#define NBG  64         // B * NH
#define NBLK 256        // proj blocks per batch (S/64)

// ---------------- scratch (device globals; no allocation allowed) ----------
__device__ __align__(16) float  g_vfull[Bdim*Cdim*S];          // raw v projection (full res)
__device__ __align__(16) float2 g_ps[3*Bdim*32*NBLK];          // stats partials (sum, sumsq)
__device__ __align__(16) float  g_pp[2*Bdim*Cdim*NTOK*4];      // pooled partials q,k: [w][b][c][n][sy]
__device__ __align__(16) float  g_mu[3][NBG];
__device__ __align__(16) float  g_rs[3][NBG];
__device__ __align__(16) float  g_qp[NBG*NTOK*DHEAD];          // pooled, normed, *0.5 (scale folded)
__device__ __align__(16) float  g_kp[NBG*NTOK*DHEAD];
__device__ __align__(16) float  g_vn[NBG*NTOK*64];             // normalized V, PRE-ROUNDED to tf32 bits

// flash dynamic smem layout (floats):
//   pt   [64*68]  P tile (tf32 bits), stride 68 -> A frags conflict-free
//   vt   [64*72]  V tile (tf32 bits), stride 72 -> B frags conflict-free
//   rsum [64]
//   tab  [TABSZ]  this head's rel_table slice
#define PT_OFF   0
#define VT_OFF   (64*68)
#define RS_OFF   (VT_OFF + 64*72)
#define TAB_OFF  (RS_OFF + 64)
#define DYN_FLOATS (TAB_OFF + TABSZ + 1)
#define DYN_BYTES  (DYN_FLOATS * 4)

// ---------------- helpers ---------------------------------------------------
__device__ __forceinline__ unsigned f2tf32(float x) {
    unsigned r;
    asm("cvt.rna.tf32.f32 %0, %1;" : "=r"(r) : "f"(x));
    return r;
}
__device__ __forceinline__ void mma_tf32(float c[4],
                                         unsigned a0, unsigned a1, unsigned a2, unsigned a3,
                                         unsigned b0, unsigned b1) {
    asm volatile("mma.sync.aligned.m16n8k8.row.col.f32.tf32.tf32.f32 "
                 "{%0,%1,%2,%3}, {%4,%5,%6,%7}, {%8,%9}, {%0,%1,%2,%3};"
                 : "+f"(c[0]), "+f"(c[1]), "+f"(c[2]), "+f"(c[3])
                 : "r"(a0), "r"(a1), "r"(a2), "r"(a3), "r"(b0), "r"(b1));
}

// ---------------- K1: projections + fused pooling/stats partials -----------
// y[m, s] = sum_c W[m,c] * x[b, c, s];  M=128, N=16384, K=128.
// One block = one 64-col slice (exactly one (t,y) image row) of one batch.
// x tile staged once, reused for all three W matrices (W split-compensated).
// q,k are NOT written full-res: 4-pixel x-patch sums go to g_pp, GroupNorm
// stats partials (all three tensors) go to g_ps. Only v is stored full-res.
__global__ __launch_bounds__(256) void proj_mma(const float* __restrict__ x,
                                                const float* __restrict__ Wq,
                                                const float* __restrict__ Wk,
                                                const float* __restrict__ Wv) {
    int b  = blockIdx.y;
    int n0 = blockIdx.x * 64;
    int t  = n0 >> 12, y = (n0 >> 6) & 63;
    int hy = y >> 2,  sy = y & 3;
    const float* X = x + (size_t)b * Cdim * S;

    __shared__ float xs[128][72];   // tf32 bits; stride 72 -> conflict-free B frags

    int tid = threadIdx.x;
    for (int i = tid; i < 128 * 16; i += 256) {
        int c = i >> 4, n4 = (i & 15) * 4;
        float4 v = *reinterpret_cast<const float4*>(&X[(size_t)c * S + n0 + n4]);
        float4 o;
        o.x = __uint_as_float(f2tf32(v.x));
        o.y = __uint_as_float(f2tf32(v.y));
        o.z = __uint_as_float(f2tf32(v.z));
        o.w = __uint_as_float(f2tf32(v.w));
        *reinterpret_cast<float4*>(&xs[c][n4]) = o;
    }
    __syncthreads();

    int w = tid >> 5, lane = tid & 31;
    int gid = lane >> 2, tig = lane & 3;
    int m0 = w * 16;                 // warp owns 16 output rows (channels)

    #pragma unroll 1
    for (int which = 0; which < 3; which++) {
        const float* Wm = (which == 0) ? Wq : (which == 1 ? Wk : Wv);
        float acc[8][4];
        #pragma unroll
        for (int ct = 0; ct < 8; ct++)
            #pragma unroll
            for (int r = 0; r < 4; r++) acc[ct][r] = 0.f;

        #pragma unroll 2
        for (int k8 = 0; k8 < 16; k8++) {
            int kb = k8 * 8;
            float w0 = Wm[(m0 + gid    ) * Cdim + kb + tig    ];
            float w1 = Wm[(m0 + gid + 8) * Cdim + kb + tig    ];
            float w2 = Wm[(m0 + gid    ) * Cdim + kb + tig + 4];
            float w3 = Wm[(m0 + gid + 8) * Cdim + kb + tig + 4];
            unsigned a0 = f2tf32(w0), a1 = f2tf32(w1), a2 = f2tf32(w2), a3 = f2tf32(w3);
            unsigned l0 = f2tf32(w0 - __uint_as_float(a0));
            unsigned l1 = f2tf32(w1 - __uint_as_float(a1));
            unsigned l2 = f2tf32(w2 - __uint_as_float(a2));
            unsigned l3 = f2tf32(w3 - __uint_as_float(a3));
            #pragma unroll
            for (int ct = 0; ct < 8; ct++) {
                unsigned b0 = __float_as_uint(xs[kb + tig    ][ct * 8 + gid]);
                unsigned b1 = __float_as_uint(xs[kb + tig + 4][ct * 8 + gid]);
                mma_tf32(acc[ct], a0, a1, a2, a3, b0, b1);
                mma_tf32(acc[ct], l0, l1, l2, l3, b0, b1);
            }
        }

        if (which == 2) {
            // v: store full-res (needed at pixel granularity)
            float* Y = g_vfull + (size_t)b * Cdim * S;
            #pragma unroll
            for (int ct = 0; ct < 8; ct++) {
                int n = n0 + ct * 8 + tig * 2;
                *reinterpret_cast<float2*>(&Y[(size_t)(m0 + gid    ) * S + n]) =
                    make_float2(acc[ct][0], acc[ct][1]);
                *reinterpret_cast<float2*>(&Y[(size_t)(m0 + gid + 8) * S + n]) =
                    make_float2(acc[ct][2], acc[ct][3]);
            }
        } else {
            // q,k: 4-pixel x-patch partial sums -> g_pp[which][b][c][n][sy]
            #pragma unroll
            for (int ct = 0; ct < 8; ct++) {
                float p0 = acc[ct][0] + acc[ct][1];   // row m0+gid
                float p1 = acc[ct][2] + acc[ct][3];   // row m0+gid+8
                p0 += __shfl_xor_sync(0xffffffffu, p0, 1);
                p1 += __shfl_xor_sync(0xffffffffu, p1, 1);
                if ((lane & 1) == 0) {
                    int px = ct * 2 + ((lane >> 1) & 1);
                    int n  = t * 256 + hy * 16 + px;
                    size_t base = ((size_t)(which * Bdim + b) * Cdim);
                    g_pp[((base + m0 + gid    ) * NTOK + n) * 4 + sy] = p0;
                    g_pp[((base + m0 + gid + 8) * NTOK + n) * 4 + sy] = p1;
                }
            }
        }

        // stats partials (all three tensors)
        float s0 = 0.f, ss0 = 0.f, s1 = 0.f, ss1 = 0.f;
        #pragma unroll
        for (int ct = 0; ct < 8; ct++) {
            s0  += acc[ct][0] + acc[ct][1];
            ss0 += acc[ct][0] * acc[ct][0] + acc[ct][1] * acc[ct][1];
            s1  += acc[ct][2] + acc[ct][3];
            ss1 += acc[ct][2] * acc[ct][2] + acc[ct][3] * acc[ct][3];
        }
        #pragma unroll
        for (int o = 1; o <= 8; o <<= 1) {
            s0  += __shfl_xor_sync(0xffffffffu, s0,  o);
            ss0 += __shfl_xor_sync(0xffffffffu, ss0, o);
            s1  += __shfl_xor_sync(0xffffffffu, s1,  o);
            ss1 += __shfl_xor_sync(0xffffffffu, ss1, o);
        }
        if (lane == 0 || lane == 16) {
            int grp = (m0 >> 2) + (lane >> 4);
            size_t base = (size_t)(which * Bdim + b) * 32;
            g_ps[(base + grp    ) * NBLK + blockIdx.x] = make_float2(s0, ss0);
            g_ps[(base + grp + 2) * NBLK + blockIdx.x] = make_float2(s1, ss1);
        }
    }
}

// ---------------- K2: groupnorm stats from partials (192 tiny blocks) ------
__global__ void stats_kernel() {
    int w  = blockIdx.x / NBG;   // 0..2  (q,k,v)
    int bg = blockIdx.x % NBG;
    int b = bg >> 5, g = bg & 31;
    const float2* ps = g_ps + ((size_t)(w * Bdim + b) * 32 + g) * NBLK;
    int tid = threadIdx.x;       // 256 threads, one partial each
    float2 v = ps[tid];
    __shared__ float sh1[256], sh2[256];
    sh1[tid] = v.x; sh2[tid] = v.y;
    __syncthreads();
    for (int o = 128; o > 0; o >>= 1) {
        if (tid < o) { sh1[tid] += sh1[tid + o]; sh2[tid] += sh2[tid + o]; }
        __syncthreads();
    }
    if (tid == 0) {
        float inv = 1.0f / (4.0f * S);
        float mu  = sh1[0] * inv;
        float var = sh2[0] * inv - mu * mu;
        g_mu[w][bg] = mu;
        g_rs[w][bg] = rsqrtf(var + 1e-5f);
    }
}

// ---------------- K3: pooled Q/K (from partials) + normalized V ------------
// V is stored ALREADY tf32-rounded (bit patterns) since its only consumer is
// the flash mma B-operand — conversion happens once here, not 16x in flash.
__global__ void build_kernel(const float* __restrict__ gq_g, const float* __restrict__ gq_b,
                             const float* __restrict__ gk_g, const float* __restrict__ gk_b,
                             const float* __restrict__ gv_g, const float* __restrict__ gv_b) {
    int idx = blockIdx.x * blockDim.x + threadIdx.x;
    if (idx >= NBG * NTOK * DHEAD) return;
    int dd = idx & 3;
    int n  = (idx >> 2) & (NTOK - 1);
    int bg = idx >> 12;
    int b = bg >> 5, g = bg & 31;
    int c = g * 4 + dd;
    int t = n >> 8, hy = (n >> 4) & 15, wx = n & 15;
    int sbase = t * 4096 + hy * 4 * 64 + wx * 4;

    float4 q4 = *reinterpret_cast<const float4*>(
        &g_pp[(((size_t)(0 * Bdim + b) * Cdim + c) * NTOK + n) * 4]);
    float4 k4 = *reinterpret_cast<const float4*>(
        &g_pp[(((size_t)(1 * Bdim + b) * Cdim + c) * NTOK + n) * 4]);
    float qs = q4.x + q4.y + q4.z + q4.w;
    float ks = k4.x + k4.y + k4.z + k4.w;

    const float* vr = g_vfull + (size_t)(b * Cdim + c) * S;
    float muv = g_mu[2][bg], rsv = g_rs[2][bg];
    float gvw = gv_g[c], bvw = gv_b[c];
    float* vdst = g_vn + (size_t)bg * (NTOK * 64) + n * 64 + dd * 16;

    #pragma unroll
    for (int sy = 0; sy < 4; sy++) {
        float4 vv4 = *reinterpret_cast<const float4*>(vr + sbase + sy * 64);
        float4 vo;
        vo.x = __uint_as_float(f2tf32((vv4.x - muv) * rsv * gvw + bvw));
        vo.y = __uint_as_float(f2tf32((vv4.y - muv) * rsv * gvw + bvw));
        vo.z = __uint_as_float(f2tf32((vv4.z - muv) * rsv * gvw + bvw));
        vo.w = __uint_as_float(f2tf32((vv4.w - muv) * rsv * gvw + bvw));
        *reinterpret_cast<float4*>(vdst + sy * 4) = vo;
    }
    float qv = ((qs * 0.0625f - g_mu[0][bg]) * g_rs[0][bg] * gq_g[c] + gq_b[c]) * 0.5f;
    float kv = (ks * 0.0625f - g_mu[1][bg]) * g_rs[1][bg] * gk_g[c] + gk_b[c];
    g_qp[(size_t)bg * (NTOK * DHEAD) + n * 4 + dd] = qv;
    g_kp[(size_t)bg * (NTOK * DHEAD) + n * 4 + dd] = kv;
}

// ---------------- K4: fused flash attention --------------------------------
// Softmax WITHOUT max subtraction (logits provably tiny for pooled groupnorm
// q/k; shift-invariance exact). Per-thread row-sum partials; one width-16
// reduction at the end.
// The head's rel_table slice (27 KB) is staged into dynamic smem once per
// block: converts scattered L1 gathers (8-16 wavefronts each) into LDS with
// small conflict degree — the dominant phase-1 cost in the cycle model.
// Phase 1 (fp32): logits + analytic rel-pos bias + exp; P -> smem (tf32, STS.128).
// Phase 2 (tensor core): warp-tiled m16n8k8 tf32 mma, out += P @ V.
// rel_index is analytic: idx = dt*961 + dy*31 + dx + 3363.
__global__ __launch_bounds__(256) void flash_kernel(const float* __restrict__ rel_table,
                                                    float* __restrict__ out) {
    extern __shared__ float dyn[];
    float* pt      = dyn + PT_OFF;    // [64][68]
    float* vt      = dyn + VT_OFF;    // [64][72]
    float* sh_rsum = dyn + RS_OFF;    // [64]
    float* sh_tab  = dyn + TAB_OFF;   // [TABSZ]

    int bg = blockIdx.y;
    int n0 = blockIdx.x * 64;
    int b = bg >> 5, g = bg & 31;
    const float*  tab = rel_table + (size_t)g * TABSZ;
    const float4* qp4 = reinterpret_cast<const float4*>(g_qp + (size_t)bg * NTOK * DHEAD);
    const float4* kp4 = reinterpret_cast<const float4*>(g_kp + (size_t)bg * NTOK * DHEAD);
    const float*  V   = g_vn + (size_t)bg * (NTOK * 64);

    int tid = threadIdx.x;
    int tx = tid & 15, ty = tid >> 4;
    int w = tid >> 5, lane = tid & 31;
    int gid = lane >> 2, tig = lane & 3;
    int rg = w & 3;       // row group: rows rg*16 .. rg*16+15
    int ch = w >> 2;      // col half:  cols ch*32 .. ch*32+31

    // stage this head's bias table (coalesced)
    for (int i = tid; i < TABSZ; i += 256) sh_tab[i] = tab[i];

    float4 q[4];
    int rbase[4];
    #pragma unroll
    for (int i = 0; i < 4; i++) {
        int r = n0 + ty * 4 + i;
        q[i] = qp4[r];
        rbase[i] = (r >> 8) * 961 + ((r >> 4) & 15) * 31 + (r & 15) + 3363;
    }
    float rsum[4] = {};               // per-thread partial row sums
    float acc[4][4];                  // [col-tile][mma C regs], persists across m-tiles
    #pragma unroll
    for (int ct = 0; ct < 4; ct++)
        #pragma unroll
        for (int r = 0; r < 4; r++) acc[ct][r] = 0.f;

    __syncthreads();   // table staged

    for (int m0 = 0; m0 < NTOK; m0 += 64) {
        // (1) issue V-tile loads into registers (latency hidden by phase 1)
        float4 vreg[4];
        #pragma unroll
        for (int s = 0; s < 4; s++) {
            int i = tid + s * 256;
            int m = i >> 4, f4 = (i & 15) * 4;
            vreg[s] = *reinterpret_cast<const float4*>(&V[(size_t)(m0 + m) * 64 + f4]);
        }

        // (2) this thread's 4 key columns
        float4 km[4];
        int mval[4];
        #pragma unroll
        for (int j = 0; j < 4; j++) {
            int m = m0 + tx * 4 + j;
            km[j] = kp4[m];
            mval[j] = (m >> 8) * 961 + ((m >> 4) & 15) * 31 + (m & 15);
        }

        if (m0) __syncthreads();   // previous phase 2 done reading pt/vt

        // (3) phase 1: logits + exp; P -> smem (vectorized STS.128)
        #pragma unroll
        for (int i = 0; i < 4; i++) {
            float l[4];
            #pragma unroll
            for (int j = 0; j < 4; j++) {
                l[j] = q[i].x * km[j].x + q[i].y * km[j].y
                     + q[i].z * km[j].z + q[i].w * km[j].w
                     + sh_tab[rbase[i] - mval[j]];
            }
            #pragma unroll
            for (int j = 0; j < 4; j++) l[j] = __expf(l[j]);
            rsum[i] += l[0] + l[1] + l[2] + l[3];
            float4 pv;
            pv.x = __uint_as_float(f2tf32(l[0]));
            pv.y = __uint_as_float(f2tf32(l[1]));
            pv.z = __uint_as_float(f2tf32(l[2]));
            pv.w = __uint_as_float(f2tf32(l[3]));
            *reinterpret_cast<float4*>(&pt[(ty * 4 + i) * 68 + tx * 4]) = pv;
        }

        // (4) store the V tile (pre-rounded; pure copy, loads long since landed)
        #pragma unroll
        for (int s = 0; s < 4; s++) {
            int i = tid + s * 256;
            int m = i >> 4, f4 = (i & 15) * 4;
            *reinterpret_cast<float4*>(&vt[m * 72 + f4]) = vreg[s];
        }
        __syncthreads();   // pt + vt ready

        // (5) phase 2: mma over this 64-key tile (no rescale needed)
        #pragma unroll
        for (int k8 = 0; k8 < 8; k8++) {
            int kb = k8 * 8;
            unsigned a0 = __float_as_uint(pt[(rg * 16 + gid    ) * 68 + kb + tig    ]);
            unsigned a1 = __float_as_uint(pt[(rg * 16 + gid + 8) * 68 + kb + tig    ]);
            unsigned a2 = __float_as_uint(pt[(rg * 16 + gid    ) * 68 + kb + tig + 4]);
            unsigned a3 = __float_as_uint(pt[(rg * 16 + gid + 8) * 68 + kb + tig + 4]);
            #pragma unroll
            for (int ct = 0; ct < 4; ct++) {
                int f = ch * 32 + ct * 8 + gid;
                unsigned b0 = __float_as_uint(vt[(kb + tig    ) * 72 + f]);
                unsigned b1 = __float_as_uint(vt[(kb + tig + 4) * 72 + f]);
                mma_tf32(acc[ct], a0, a1, a2, a3, b0, b1);
            }
        }
    }

    // single row-sum reduction (width 16), then hand off via smem
    #pragma unroll
    for (int i = 0; i < 4; i++) {
        #pragma unroll
        for (int o = 8; o > 0; o >>= 1)
            rsum[i] += __shfl_xor_sync(0xffffffffu, rsum[i], o, 16);
    }
    __syncthreads();
    if (tx == 0) {
        #pragma unroll
        for (int i = 0; i < 4; i++) sh_rsum[ty * 4 + i] = rsum[i];
    }
    __syncthreads();

    // epilogue: normalize + scatter directly to (B,C,T,H,W)
    float inv0 = 1.0f / sh_rsum[rg * 16 + gid];
    float inv1 = 1.0f / sh_rsum[rg * 16 + gid + 8];
    int ra = n0 + rg * 16 + gid;
    int rbrow = ra + 8;
    int ta = ra >> 8,   hya = (ra >> 4) & 15,   wxa = ra & 15;
    int tb = rbrow >> 8, hyb = (rbrow >> 4) & 15, wxb = rbrow & 15;
    #pragma unroll
    for (int ct = 0; ct < 4; ct++) {
        int f0 = ch * 32 + ct * 8 + tig * 2;
        int dd = f0 >> 4, p = f0 & 15;
        int sy = p >> 2, sx = p & 3;
        int c  = g * 4 + dd;
        size_t cb = (size_t)(b * Cdim + c) * Tdim;
        size_t offa = (cb + ta) * 4096 + (size_t)(hya * 4 + sy) * 64 + wxa * 4 + sx;
        size_t offb = (cb + tb) * 4096 + (size_t)(hyb * 4 + sy) * 64 + wxb * 4 + sx;
        *reinterpret_cast<float2*>(out + offa) = make_float2(acc[ct][0] * inv0, acc[ct][1] * inv0);
        *reinterpret_cast<float2*>(out + offb) = make_float2(acc[ct][2] * inv1, acc[ct][3] * inv1);
    }
}

// ---------------- launch ----------------------------------------------------
extern "C" void kernel_launch(void* const* d_in, const int* in_sizes, int n_in,
                              void* d_out, int out_size) {
    const float* x    = (const float*)d_in[0];
    const float* Wq   = (const float*)d_in[1];
    const float* Wk   = (const float*)d_in[2];
    const float* Wv   = (const float*)d_in[3];
    const float* gq_g = (const float*)d_in[4];
    const float* gq_b = (const float*)d_in[5];
    const float* gk_g = (const float*)d_in[6];
    const float* gk_b = (const float*)d_in[7];
    const float* gv_g = (const float*)d_in[8];
    const float* gv_b = (const float*)d_in[9];
    const float* rel_table = (const float*)d_in[10];
    float* out = (float*)d_out;

    // deterministic, no guards: set every call (no-op after the first)
    cudaFuncSetAttribute(flash_kernel, cudaFuncAttributeMaxDynamicSharedMemorySize, DYN_BYTES);

    proj_mma<<<dim3(NBLK, Bdim), 256>>>(x, Wq, Wk, Wv);
    stats_kernel<<<3 * NBG, 256>>>();
    build_kernel<<<(NBG * NTOK * DHEAD + 255) / 256, 256>>>(gq_g, gq_b, gk_g, gk_b, gv_g, gv_b);
    flash_kernel<<<dim3(NTOK / 64, NBG), 256, DYN_BYTES>>>(rel_table, out);
}

// round 13
// speedup vs baseline: 1.0857x; 1.0857x over previous
#include <cuda_runtime.h>

#define Bdim 2
#define Cdim 128
#define Tdim 4
#define S    16384      // T*H*W
#define NH   32
#define DHEAD 4
#define NTOK 1024       // T * (H/4) * (W/4)
#define TABSZ 6727      // (2T-1)*(2h-1)*(2w-1) = 7*31*31
#define NBG  64         // B * NH
#define NBLK 256        // proj blocks per batch (S/64)

// ---------------- scratch (device globals; no allocation allowed) ----------
__device__ __align__(16) float  g_vfull[Bdim*Cdim*S];          // raw v projection (full res)
__device__ __align__(16) float2 g_ps[3*Bdim*32*NBLK];          // stats partials (sum, sumsq)
__device__ __align__(16) float  g_pp[2*Bdim*Cdim*NTOK*4];      // pooled partials q,k: [w][b][c][n][sy]
__device__ __align__(16) float  g_mu[3][NBG];
__device__ __align__(16) float  g_rs[3][NBG];
__device__ __align__(16) float  g_qp[NBG*NTOK*DHEAD];          // pooled, normed, *0.5 (scale folded)
__device__ __align__(16) float  g_kp[NBG*NTOK*DHEAD];
__device__ __align__(16) float  g_vn[NBG*NTOK*64];             // normalized V, PRE-ROUNDED to tf32 bits

// flash dynamic smem layout (floats):
//   pt   [64*68]  P tile (tf32 bits), stride 68 -> A frags conflict-free
//   vt   [64*72]  V tile (tf32 bits), stride 72 -> B frags conflict-free
//   rsum [64]
//   tab  [TABSZ]  this head's rel_table slice
#define PT_OFF   0
#define VT_OFF   (64*68)
#define RS_OFF   (VT_OFF + 64*72)
#define TAB_OFF  (RS_OFF + 64)
#define DYN_FLOATS (TAB_OFF + TABSZ + 1)
#define DYN_BYTES  (DYN_FLOATS * 4)

// ---------------- helpers ---------------------------------------------------
__device__ __forceinline__ unsigned f2tf32(float x) {
    unsigned r;
    asm("cvt.rna.tf32.f32 %0, %1;" : "=r"(r) : "f"(x));
    return r;
}
__device__ __forceinline__ void mma_tf32(float c[4],
                                         unsigned a0, unsigned a1, unsigned a2, unsigned a3,
                                         unsigned b0, unsigned b1) {
    asm volatile("mma.sync.aligned.m16n8k8.row.col.f32.tf32.tf32.f32 "
                 "{%0,%1,%2,%3}, {%4,%5,%6,%7}, {%8,%9}, {%0,%1,%2,%3};"
                 : "+f"(c[0]), "+f"(c[1]), "+f"(c[2]), "+f"(c[3])
                 : "r"(a0), "r"(a1), "r"(a2), "r"(a3), "r"(b0), "r"(b1));
}

// ---------------- K1: projections + fused pooling/stats partials -----------
// y[m, s] = sum_c W[m,c] * x[b, c, s];  M=128, N=16384, K=128.
// One block = one 64-col slice (exactly one (t,y) image row) of one batch.
// x tile staged once, reused for all three W matrices (W split-compensated).
// q,k are NOT written full-res: 4-pixel x-patch sums go to g_pp, GroupNorm
// stats partials (all three tensors) go to g_ps. Only v is stored full-res.
__global__ __launch_bounds__(256) void proj_mma(const float* __restrict__ x,
                                                const float* __restrict__ Wq,
                                                const float* __restrict__ Wk,
                                                const float* __restrict__ Wv) {
    int b  = blockIdx.y;
    int n0 = blockIdx.x * 64;
    int t  = n0 >> 12, y = (n0 >> 6) & 63;
    int hy = y >> 2,  sy = y & 3;
    const float* X = x + (size_t)b * Cdim * S;

    __shared__ float xs[128][72];   // tf32 bits; stride 72 -> conflict-free B frags

    int tid = threadIdx.x;
    for (int i = tid; i < 128 * 16; i += 256) {
        int c = i >> 4, n4 = (i & 15) * 4;
        float4 v = *reinterpret_cast<const float4*>(&X[(size_t)c * S + n0 + n4]);
        float4 o;
        o.x = __uint_as_float(f2tf32(v.x));
        o.y = __uint_as_float(f2tf32(v.y));
        o.z = __uint_as_float(f2tf32(v.z));
        o.w = __uint_as_float(f2tf32(v.w));
        *reinterpret_cast<float4*>(&xs[c][n4]) = o;
    }
    __syncthreads();

    int w = tid >> 5, lane = tid & 31;
    int gid = lane >> 2, tig = lane & 3;
    int m0 = w * 16;                 // warp owns 16 output rows (channels)

    #pragma unroll 1
    for (int which = 0; which < 3; which++) {
        const float* Wm = (which == 0) ? Wq : (which == 1 ? Wk : Wv);
        float acc[8][4];
        #pragma unroll
        for (int ct = 0; ct < 8; ct++)
            #pragma unroll
            for (int r = 0; r < 4; r++) acc[ct][r] = 0.f;

        #pragma unroll 2
        for (int k8 = 0; k8 < 16; k8++) {
            int kb = k8 * 8;
            float w0 = Wm[(m0 + gid    ) * Cdim + kb + tig    ];
            float w1 = Wm[(m0 + gid + 8) * Cdim + kb + tig    ];
            float w2 = Wm[(m0 + gid    ) * Cdim + kb + tig + 4];
            float w3 = Wm[(m0 + gid + 8) * Cdim + kb + tig + 4];
            unsigned a0 = f2tf32(w0), a1 = f2tf32(w1), a2 = f2tf32(w2), a3 = f2tf32(w3);
            unsigned l0 = f2tf32(w0 - __uint_as_float(a0));
            unsigned l1 = f2tf32(w1 - __uint_as_float(a1));
            unsigned l2 = f2tf32(w2 - __uint_as_float(a2));
            unsigned l3 = f2tf32(w3 - __uint_as_float(a3));
            #pragma unroll
            for (int ct = 0; ct < 8; ct++) {
                unsigned b0 = __float_as_uint(xs[kb + tig    ][ct * 8 + gid]);
                unsigned b1 = __float_as_uint(xs[kb + tig + 4][ct * 8 + gid]);
                mma_tf32(acc[ct], a0, a1, a2, a3, b0, b1);
                mma_tf32(acc[ct], l0, l1, l2, l3, b0, b1);
            }
        }

        if (which == 2) {
            // v: store full-res (needed at pixel granularity)
            float* Y = g_vfull + (size_t)b * Cdim * S;
            #pragma unroll
            for (int ct = 0; ct < 8; ct++) {
                int n = n0 + ct * 8 + tig * 2;
                *reinterpret_cast<float2*>(&Y[(size_t)(m0 + gid    ) * S + n]) =
                    make_float2(acc[ct][0], acc[ct][1]);
                *reinterpret_cast<float2*>(&Y[(size_t)(m0 + gid + 8) * S + n]) =
                    make_float2(acc[ct][2], acc[ct][3]);
            }
        } else {
            // q,k: 4-pixel x-patch partial sums -> g_pp[which][b][c][n][sy]
            #pragma unroll
            for (int ct = 0; ct < 8; ct++) {
                float p0 = acc[ct][0] + acc[ct][1];   // row m0+gid
                float p1 = acc[ct][2] + acc[ct][3];   // row m0+gid+8
                p0 += __shfl_xor_sync(0xffffffffu, p0, 1);
                p1 += __shfl_xor_sync(0xffffffffu, p1, 1);
                if ((lane & 1) == 0) {
                    int px = ct * 2 + ((lane >> 1) & 1);
                    int n  = t * 256 + hy * 16 + px;
                    size_t base = ((size_t)(which * Bdim + b) * Cdim);
                    g_pp[((base + m0 + gid    ) * NTOK + n) * 4 + sy] = p0;
                    g_pp[((base + m0 + gid + 8) * NTOK + n) * 4 + sy] = p1;
                }
            }
        }

        // stats partials (all three tensors)
        float s0 = 0.f, ss0 = 0.f, s1 = 0.f, ss1 = 0.f;
        #pragma unroll
        for (int ct = 0; ct < 8; ct++) {
            s0  += acc[ct][0] + acc[ct][1];
            ss0 += acc[ct][0] * acc[ct][0] + acc[ct][1] * acc[ct][1];
            s1  += acc[ct][2] + acc[ct][3];
            ss1 += acc[ct][2] * acc[ct][2] + acc[ct][3] * acc[ct][3];
        }
        #pragma unroll
        for (int o = 1; o <= 8; o <<= 1) {
            s0  += __shfl_xor_sync(0xffffffffu, s0,  o);
            ss0 += __shfl_xor_sync(0xffffffffu, ss0, o);
            s1  += __shfl_xor_sync(0xffffffffu, s1,  o);
            ss1 += __shfl_xor_sync(0xffffffffu, ss1, o);
        }
        if (lane == 0 || lane == 16) {
            int grp = (m0 >> 2) + (lane >> 4);
            size_t base = (size_t)(which * Bdim + b) * 32;
            g_ps[(base + grp    ) * NBLK + blockIdx.x] = make_float2(s0, ss0);
            g_ps[(base + grp + 2) * NBLK + blockIdx.x] = make_float2(s1, ss1);
        }
    }
}

// ---------------- K2: groupnorm stats from partials (192 tiny blocks) ------
__global__ void stats_kernel() {
    int w  = blockIdx.x / NBG;   // 0..2  (q,k,v)
    int bg = blockIdx.x % NBG;
    int b = bg >> 5, g = bg & 31;
    const float2* ps = g_ps + ((size_t)(w * Bdim + b) * 32 + g) * NBLK;
    int tid = threadIdx.x;       // 256 threads, one partial each
    float2 v = ps[tid];
    __shared__ float sh1[256], sh2[256];
    sh1[tid] = v.x; sh2[tid] = v.y;
    __syncthreads();
    for (int o = 128; o > 0; o >>= 1) {
        if (tid < o) { sh1[tid] += sh1[tid + o]; sh2[tid] += sh2[tid + o]; }
        __syncthreads();
    }
    if (tid == 0) {
        float inv = 1.0f / (4.0f * S);
        float mu  = sh1[0] * inv;
        float var = sh2[0] * inv - mu * mu;
        g_mu[w][bg] = mu;
        g_rs[w][bg] = rsqrtf(var + 1e-5f);
    }
}

// ---------------- K3: pooled Q/K (from partials) + normalized V ------------
// V is stored ALREADY tf32-rounded (bit patterns) since its only consumer is
// the flash mma B-operand — conversion happens once here, not 16x in flash.
__global__ void build_kernel(const float* __restrict__ gq_g, const float* __restrict__ gq_b,
                             const float* __restrict__ gk_g, const float* __restrict__ gk_b,
                             const float* __restrict__ gv_g, const float* __restrict__ gv_b) {
    int idx = blockIdx.x * blockDim.x + threadIdx.x;
    if (idx >= NBG * NTOK * DHEAD) return;
    int dd = idx & 3;
    int n  = (idx >> 2) & (NTOK - 1);
    int bg = idx >> 12;
    int b = bg >> 5, g = bg & 31;
    int c = g * 4 + dd;
    int t = n >> 8, hy = (n >> 4) & 15, wx = n & 15;
    int sbase = t * 4096 + hy * 4 * 64 + wx * 4;

    float4 q4 = *reinterpret_cast<const float4*>(
        &g_pp[(((size_t)(0 * Bdim + b) * Cdim + c) * NTOK + n) * 4]);
    float4 k4 = *reinterpret_cast<const float4*>(
        &g_pp[(((size_t)(1 * Bdim + b) * Cdim + c) * NTOK + n) * 4]);
    float qs = q4.x + q4.y + q4.z + q4.w;
    float ks = k4.x + k4.y + k4.z + k4.w;

    const float* vr = g_vfull + (size_t)(b * Cdim + c) * S;
    float muv = g_mu[2][bg], rsv = g_rs[2][bg];
    float gvw = gv_g[c], bvw = gv_b[c];
    float* vdst = g_vn + (size_t)bg * (NTOK * 64) + n * 64 + dd * 16;

    #pragma unroll
    for (int sy = 0; sy < 4; sy++) {
        float4 vv4 = *reinterpret_cast<const float4*>(vr + sbase + sy * 64);
        float4 vo;
        vo.x = __uint_as_float(f2tf32((vv4.x - muv) * rsv * gvw + bvw));
        vo.y = __uint_as_float(f2tf32((vv4.y - muv) * rsv * gvw + bvw));
        vo.z = __uint_as_float(f2tf32((vv4.z - muv) * rsv * gvw + bvw));
        vo.w = __uint_as_float(f2tf32((vv4.w - muv) * rsv * gvw + bvw));
        *reinterpret_cast<float4*>(vdst + sy * 4) = vo;
    }
    float qv = ((qs * 0.0625f - g_mu[0][bg]) * g_rs[0][bg] * gq_g[c] + gq_b[c]) * 0.5f;
    float kv = (ks * 0.0625f - g_mu[1][bg]) * g_rs[1][bg] * gk_g[c] + gk_b[c];
    g_qp[(size_t)bg * (NTOK * DHEAD) + n * 4 + dd] = qv;
    g_kp[(size_t)bg * (NTOK * DHEAD) + n * 4 + dd] = kv;
}

// ---------------- K4: fused flash attention --------------------------------
// Occupancy was REGISTER-limited (118 regs -> 2 CTAs/SM, occ 23%, issue 40%).
// (a) __launch_bounds__(256,3) targets <=85 regs -> 3 CTAs (37.5%).
// (b) V tile staged via cp.async (LDGSTS): no register round-trip (frees the
//     16-reg vreg prefetch), still overlapped with phase-1 compute.
// Softmax WITHOUT max subtraction (logits provably tiny; shift-invariance
// exact). Per-thread row-sum partials; one width-16 reduction at the end.
// Head's rel_table slice staged in dynamic smem (27 KB).
// Phase 1 (fp32): logits + analytic bias + exp; P -> smem (tf32, STS.128).
// Phase 2 (tensor core): warp-tiled m16n8k8 tf32 mma, out += P @ V.
// rel_index is analytic: idx = dt*961 + dy*31 + dx + 3363.
__global__ void __launch_bounds__(256, 3) flash_kernel(const float* __restrict__ rel_table,
                                                       float* __restrict__ out) {
    extern __shared__ float dyn[];
    float* pt      = dyn + PT_OFF;    // [64][68]
    float* vt      = dyn + VT_OFF;    // [64][72]
    float* sh_rsum = dyn + RS_OFF;    // [64]
    float* sh_tab  = dyn + TAB_OFF;   // [TABSZ]

    int bg = blockIdx.y;
    int n0 = blockIdx.x * 64;
    int b = bg >> 5, g = bg & 31;
    const float*  tab = rel_table + (size_t)g * TABSZ;
    const float4* qp4 = reinterpret_cast<const float4*>(g_qp + (size_t)bg * NTOK * DHEAD);
    const float4* kp4 = reinterpret_cast<const float4*>(g_kp + (size_t)bg * NTOK * DHEAD);
    const float*  V   = g_vn + (size_t)bg * (NTOK * 64);

    int tid = threadIdx.x;
    int tx = tid & 15, ty = tid >> 4;
    int w = tid >> 5, lane = tid & 31;
    int gid = lane >> 2, tig = lane & 3;
    int rg = w & 3;       // row group: rows rg*16 .. rg*16+15
    int ch = w >> 2;      // col half:  cols ch*32 .. ch*32+31

    // stage this head's bias table (coalesced)
    for (int i = tid; i < TABSZ; i += 256) sh_tab[i] = tab[i];

    float4 q[4];
    int rbase[4];
    #pragma unroll
    for (int i = 0; i < 4; i++) {
        int r = n0 + ty * 4 + i;
        q[i] = qp4[r];
        rbase[i] = (r >> 8) * 961 + ((r >> 4) & 15) * 31 + (r & 15) + 3363;
    }
    float rsum[4] = {};               // per-thread partial row sums
    float acc[4][4];                  // [col-tile][mma C regs], persists across m-tiles
    #pragma unroll
    for (int ct = 0; ct < 4; ct++)
        #pragma unroll
        for (int r = 0; r < 4; r++) acc[ct][r] = 0.f;

    // this thread's V-tile staging slot (fixed across tiles)
    unsigned vt_dst = (unsigned)__cvta_generic_to_shared(&vt[(tid >> 4) * 72 + (tid & 15) * 4]);

    __syncthreads();   // table staged

    for (int m0 = 0; m0 < NTOK; m0 += 64) {
        // (2) this thread's 4 key columns (register loads; no smem writes)
        float4 km[4];
        int mval[4];
        #pragma unroll
        for (int j = 0; j < 4; j++) {
            int m = m0 + tx * 4 + j;
            km[j] = kp4[m];
            mval[j] = (m >> 8) * 961 + ((m >> 4) & 15) * 31 + (m & 15);
        }

        if (m0) __syncthreads();   // previous phase 2 done reading pt/vt

        // (1) async-stage V tile: gmem -> smem, no registers; overlaps phase 1
        #pragma unroll
        for (int s = 0; s < 4; s++) {
            int i = tid + s * 256;
            int m = i >> 4, f4 = (i & 15) * 4;
            asm volatile("cp.async.cg.shared.global [%0], [%1], 16;"
                         :: "r"(vt_dst + s * 16 * 72 * 4),
                            "l"(&V[(size_t)(m0 + m) * 64 + f4]) : "memory");
        }
        asm volatile("cp.async.commit_group;" ::: "memory");

        // (3) phase 1: logits + exp; P -> smem (vectorized STS.128)
        #pragma unroll
        for (int i = 0; i < 4; i++) {
            float l[4];
            #pragma unroll
            for (int j = 0; j < 4; j++) {
                l[j] = q[i].x * km[j].x + q[i].y * km[j].y
                     + q[i].z * km[j].z + q[i].w * km[j].w
                     + sh_tab[rbase[i] - mval[j]];
            }
            #pragma unroll
            for (int j = 0; j < 4; j++) l[j] = __expf(l[j]);
            rsum[i] += l[0] + l[1] + l[2] + l[3];
            float4 pv;
            pv.x = __uint_as_float(f2tf32(l[0]));
            pv.y = __uint_as_float(f2tf32(l[1]));
            pv.z = __uint_as_float(f2tf32(l[2]));
            pv.w = __uint_as_float(f2tf32(l[3]));
            *reinterpret_cast<float4*>(&pt[(ty * 4 + i) * 68 + tx * 4]) = pv;
        }

        // (4) V tile landed?
        asm volatile("cp.async.wait_group 0;" ::: "memory");
        __syncthreads();   // pt + vt ready

        // (5) phase 2: mma over this 64-key tile (no rescale needed)
        #pragma unroll
        for (int k8 = 0; k8 < 8; k8++) {
            int kb = k8 * 8;
            unsigned a0 = __float_as_uint(pt[(rg * 16 + gid    ) * 68 + kb + tig    ]);
            unsigned a1 = __float_as_uint(pt[(rg * 16 + gid + 8) * 68 + kb + tig    ]);
            unsigned a2 = __float_as_uint(pt[(rg * 16 + gid    ) * 68 + kb + tig + 4]);
            unsigned a3 = __float_as_uint(pt[(rg * 16 + gid + 8) * 68 + kb + tig + 4]);
            #pragma unroll
            for (int ct = 0; ct < 4; ct++) {
                int f = ch * 32 + ct * 8 + gid;
                unsigned b0 = __float_as_uint(vt[(kb + tig    ) * 72 + f]);
                unsigned b1 = __float_as_uint(vt[(kb + tig + 4) * 72 + f]);
                mma_tf32(acc[ct], a0, a1, a2, a3, b0, b1);
            }
        }
    }

    // single row-sum reduction (width 16), then hand off via smem
    #pragma unroll
    for (int i = 0; i < 4; i++) {
        #pragma unroll
        for (int o = 8; o > 0; o >>= 1)
            rsum[i] += __shfl_xor_sync(0xffffffffu, rsum[i], o, 16);
    }
    __syncthreads();
    if (tx == 0) {
        #pragma unroll
        for (int i = 0; i < 4; i++) sh_rsum[ty * 4 + i] = rsum[i];
    }
    __syncthreads();

    // epilogue: normalize + scatter directly to (B,C,T,H,W)
    float inv0 = 1.0f / sh_rsum[rg * 16 + gid];
    float inv1 = 1.0f / sh_rsum[rg * 16 + gid + 8];
    int ra = n0 + rg * 16 + gid;
    int rbrow = ra + 8;
    int ta = ra >> 8,   hya = (ra >> 4) & 15,   wxa = ra & 15;
    int tb = rbrow >> 8, hyb = (rbrow >> 4) & 15, wxb = rbrow & 15;
    #pragma unroll
    for (int ct = 0; ct < 4; ct++) {
        int f0 = ch * 32 + ct * 8 + tig * 2;
        int dd = f0 >> 4, p = f0 & 15;
        int sy = p >> 2, sx = p & 3;
        int c  = g * 4 + dd;
        size_t cb = (size_t)(b * Cdim + c) * Tdim;
        size_t offa = (cb + ta) * 4096 + (size_t)(hya * 4 + sy) * 64 + wxa * 4 + sx;
        size_t offb = (cb + tb) * 4096 + (size_t)(hyb * 4 + sy) * 64 + wxb * 4 + sx;
        *reinterpret_cast<float2*>(out + offa) = make_float2(acc[ct][0] * inv0, acc[ct][1] * inv0);
        *reinterpret_cast<float2*>(out + offb) = make_float2(acc[ct][2] * inv1, acc[ct][3] * inv1);
    }
}

// ---------------- launch ----------------------------------------------------
extern "C" void kernel_launch(void* const* d_in, const int* in_sizes, int n_in,
                              void* d_out, int out_size) {
    const float* x    = (const float*)d_in[0];
    const float* Wq   = (const float*)d_in[1];
    const float* Wk   = (const float*)d_in[2];
    const float* Wv   = (const float*)d_in[3];
    const float* gq_g = (const float*)d_in[4];
    const float* gq_b = (const float*)d_in[5];
    const float* gk_g = (const float*)d_in[6];
    const float* gk_b = (const float*)d_in[7];
    const float* gv_g = (const float*)d_in[8];
    const float* gv_b = (const float*)d_in[9];
    const float* rel_table = (const float*)d_in[10];
    float* out = (float*)d_out;

    // deterministic, no guards: set every call (no-op after the first)
    cudaFuncSetAttribute(flash_kernel, cudaFuncAttributeMaxDynamicSharedMemorySize, DYN_BYTES);

    proj_mma<<<dim3(NBLK, Bdim), 256>>>(x, Wq, Wk, Wv);
    stats_kernel<<<3 * NBG, 256>>>();
    build_kernel<<<(NBG * NTOK * DHEAD + 255) / 256, 256>>>(gq_g, gq_b, gk_g, gk_b, gv_g, gv_b);
    flash_kernel<<<dim3(NTOK / 64, NBG), 256, DYN_BYTES>>>(rel_table, out);
}